// round 3
// baseline (speedup 1.0000x reference)
#include <cuda_runtime.h>

#define NN 50000
#define NE 800000
#define ET (NE + NN)        // 850000 edges incl. self loops
#define D 64
#define H 6
#define HD 384
#define BATCH 1024

// ---------------- scratch (device globals; no allocations allowed) ----------
__device__ float g_xp[(size_t)NN * HD];     // 76.8 MB: per-layer transformed feats; reused as x2^T at the end
__device__ float g_as[NN * H];
__device__ float g_ad[NN * H];
__device__ float g_m[NN * H];
__device__ float g_s[NN * H];
__device__ float g_x1[NN * D];
__device__ float g_x2[NN * D];
__device__ int   g_rowptr[NN + 1];
__device__ int   g_cursor[NN];
__device__ int   g_esrc[ET];
__device__ float g_pool[BATCH * D];

// ---------------- CSR build --------------------------------------------------
__global__ void k_init_deg() {
    int i = blockIdx.x * blockDim.x + threadIdx.x;
    if (i < NN) g_cursor[i] = 1;                 // self loop
}

__global__ void k_count(const int* __restrict__ ei) {
    int e = blockIdx.x * blockDim.x + threadIdx.x;
    if (e < NE) atomicAdd(&g_cursor[ei[NE + e]], 1);   // dst = ei[1][e]
}

// single-block exclusive scan over 50000 degrees
__global__ void k_scan() {
    __shared__ int sh[1024];
    __shared__ int carry_sh;
    int tid = threadIdx.x;
    if (tid == 0) carry_sh = 0;
    __syncthreads();
    for (int base = 0; base < NN; base += 1024) {
        int i = base + tid;
        int v = (i < NN) ? g_cursor[i] : 0;
        sh[tid] = v;
        __syncthreads();
        for (int off = 1; off < 1024; off <<= 1) {
            int t2 = (tid >= off) ? sh[tid - off] : 0;
            __syncthreads();
            sh[tid] += t2;
            __syncthreads();
        }
        int carry = carry_sh;
        if (i < NN) {
            int excl = carry + sh[tid] - v;
            g_rowptr[i] = excl;
            g_cursor[i] = excl;
        }
        __syncthreads();
        if (tid == 0) carry_sh = carry + sh[1023];
        __syncthreads();
    }
    if (tid == 0) g_rowptr[NN] = carry_sh;       // == ET
}

__global__ void k_scatter(const int* __restrict__ ei) {
    int i = blockIdx.x * blockDim.x + threadIdx.x;
    if (i < NE) {
        int s = ei[i], d = ei[NE + i];
        int pos = atomicAdd(&g_cursor[d], 1);
        g_esrc[pos] = s;
    } else if (i < ET) {
        int n = i - NE;
        int pos = atomicAdd(&g_cursor[n], 1);
        g_esrc[pos] = n;                          // self loop
    }
}

// ---------------- xp = x @ W  ([NN,64] @ [64,384]) --------------------------
__global__ void __launch_bounds__(384) k_gemm_xp(const float* __restrict__ x0,
                                                 const float* __restrict__ W, int layer) {
    __shared__ float xs[16 * 64];
    const float* __restrict__ x = (layer == 0) ? x0 : g_x1;
    int c = threadIdx.x;                // output column 0..383
    int row0 = blockIdx.x * 16;
    for (int i = c; i < 16 * 64; i += 384) {
        int r = i >> 6, k = i & 63;
        int row = row0 + r;
        xs[i] = (row < NN) ? x[row * 64 + k] : 0.f;
    }
    __syncthreads();
    float acc[16];
#pragma unroll
    for (int r = 0; r < 16; r++) acc[r] = 0.f;
#pragma unroll
    for (int k4 = 0; k4 < 16; k4++) {
        float w0 = W[(4 * k4 + 0) * HD + c];
        float w1 = W[(4 * k4 + 1) * HD + c];
        float w2 = W[(4 * k4 + 2) * HD + c];
        float w3 = W[(4 * k4 + 3) * HD + c];
#pragma unroll
        for (int r = 0; r < 16; r++) {
            float4 xv = *(const float4*)&xs[r * 64 + 4 * k4];
            acc[r] += xv.x * w0 + xv.y * w1 + xv.z * w2 + xv.w * w3;
        }
    }
#pragma unroll
    for (int r = 0; r < 16; r++) {
        int row = row0 + r;
        if (row < NN) g_xp[(size_t)row * HD + c] = acc[r];
    }
}

// ---------------- per-node attention dot products ----------------------------
// as[n,h] = sum_d xp[n,h,d]*a_src[h,d]  (and same for a_dst). warp per node.
__global__ void __launch_bounds__(256) k_attn(const float* __restrict__ asrc,
                                              const float* __restrict__ adst) {
    int warp = (blockIdx.x * blockDim.x + threadIdx.x) >> 5;
    int lane = threadIdx.x & 31;
    if (warp >= NN) return;
    const float* xpr = &g_xp[(size_t)warp * HD];
    float pa[6], pd[6];
#pragma unroll
    for (int t = 0; t < 6; t++) { pa[t] = 0.f; pd[t] = 0.f; }
#pragma unroll
    for (int j = 0; j < 12; j++) {
        int idx = lane + 32 * j;      // h = j>>1 for lane<32
        float xv = xpr[idx];
        pa[j >> 1] += xv * asrc[idx];
        pd[j >> 1] += xv * adst[idx];
    }
#pragma unroll
    for (int t = 0; t < 6; t++) {
#pragma unroll
        for (int off = 16; off; off >>= 1) {
            pa[t] += __shfl_down_sync(0xffffffffu, pa[t], off);
            pd[t] += __shfl_down_sync(0xffffffffu, pd[t], off);
        }
    }
    if (lane == 0) {
#pragma unroll
        for (int t = 0; t < 6; t++) {
            g_as[warp * 6 + t] = pa[t];
            g_ad[warp * 6 + t] = pd[t];
        }
    }
}

// ---------------- per-dst softmax stats (max, sum) ---------------------------
__global__ void __launch_bounds__(256) k_edge_ms() {
    int warp = (blockIdx.x * blockDim.x + threadIdx.x) >> 5;
    int lane = threadIdx.x & 31;
    if (warp >= NN) return;
    int n = warp;
    int beg = g_rowptr[n], end = g_rowptr[n + 1];
    float adh[6];
#pragma unroll
    for (int t = 0; t < 6; t++) adh[t] = g_ad[n * 6 + t];
    float mx[6];
#pragma unroll
    for (int t = 0; t < 6; t++) mx[t] = -1e30f;
    for (int e = beg + lane; e < end; e += 32) {
        int src = g_esrc[e];
#pragma unroll
        for (int t = 0; t < 6; t++) {
            float v = g_as[src * 6 + t] + adh[t];
            v = (v > 0.f) ? v : 0.2f * v;
            mx[t] = fmaxf(mx[t], v);
        }
    }
#pragma unroll
    for (int t = 0; t < 6; t++)
#pragma unroll
        for (int off = 16; off; off >>= 1)
            mx[t] = fmaxf(mx[t], __shfl_xor_sync(0xffffffffu, mx[t], off));
    float sm[6];
#pragma unroll
    for (int t = 0; t < 6; t++) sm[t] = 0.f;
    for (int e = beg + lane; e < end; e += 32) {
        int src = g_esrc[e];
#pragma unroll
        for (int t = 0; t < 6; t++) {
            float v = g_as[src * 6 + t] + adh[t];
            v = (v > 0.f) ? v : 0.2f * v;
            sm[t] += __expf(v - mx[t]);
        }
    }
#pragma unroll
    for (int t = 0; t < 6; t++)
#pragma unroll
        for (int off = 16; off; off >>= 1)
            sm[t] += __shfl_xor_sync(0xffffffffu, sm[t], off);
    if (lane < 6) {
        g_m[n * 6 + lane] = mx[lane];
        g_s[n * 6 + lane] = sm[lane];
    }
}

// ---------------- weighted gather-accumulate + head mean + bias --------------
// 2-edge software pipeline: 24 independent L2 loads in flight per warp iter.
__global__ void __launch_bounds__(256) k_edge_acc(const float* __restrict__ bias, int layer) {
    int warp = (blockIdx.x * blockDim.x + threadIdx.x) >> 5;
    int lane = threadIdx.x & 31;
    if (warp >= NN) return;
    float* __restrict__ xout = (layer == 0) ? g_x1 : g_x2;
    int n = warp;
    int beg = g_rowptr[n], end = g_rowptr[n + 1];
    float adh = 0.f, mh = 0.f, inv_s = 0.f;
    if (lane < 6) {
        adh = g_ad[n * 6 + lane];
        mh  = g_m[n * 6 + lane];
        inv_s = 1.f / (g_s[n * 6 + lane] + 1e-16f);
    }
    float acc[12];
#pragma unroll
    for (int j = 0; j < 12; j++) acc[j] = 0.f;

    int e = beg;
    for (; e + 1 < end; e += 2) {
        int s0 = g_esrc[e];
        int s1 = g_esrc[e + 1];
        float a0 = 0.f, a1 = 0.f;
        if (lane < 6) {
            float v0 = g_as[s0 * 6 + lane] + adh;
            float v1 = g_as[s1 * 6 + lane] + adh;
            v0 = (v0 > 0.f) ? v0 : 0.2f * v0;
            v1 = (v1 > 0.f) ? v1 : 0.2f * v1;
            a0 = __expf(v0 - mh) * inv_s;
            a1 = __expf(v1 - mh) * inv_s;
        }
        const float* x0r = &g_xp[(size_t)s0 * HD];
        const float* x1r = &g_xp[(size_t)s1 * HD];
        float v0buf[12], v1buf[12];
#pragma unroll
        for (int j = 0; j < 12; j++) {
            int idx = lane + 32 * j;
            v0buf[j] = x0r[idx];
            v1buf[j] = x1r[idx];
        }
#pragma unroll
        for (int j = 0; j < 12; j++) {
            float b0 = __shfl_sync(0xffffffffu, a0, j >> 1);
            float b1 = __shfl_sync(0xffffffffu, a1, j >> 1);
            acc[j] += b0 * v0buf[j] + b1 * v1buf[j];
        }
    }
    if (e < end) {
        int src = g_esrc[e];
        float alpha = 0.f;
        if (lane < 6) {
            float v = g_as[src * 6 + lane] + adh;
            v = (v > 0.f) ? v : 0.2f * v;
            alpha = __expf(v - mh) * inv_s;
        }
        const float* xr = &g_xp[(size_t)src * HD];
#pragma unroll
        for (int j = 0; j < 12; j++) {
            int idx = lane + 32 * j;
            float a = __shfl_sync(0xffffffffu, alpha, j >> 1);
            acc[j] += a * xr[idx];
        }
    }
    // even j -> d=lane (head j/2), odd j -> d=lane+32
    float se = 0.f, so = 0.f;
#pragma unroll
    for (int j = 0; j < 12; j += 2) { se += acc[j]; so += acc[j + 1]; }
    xout[n * 64 + lane]      = se * (1.f / 6.f) + bias[lane];
    xout[n * 64 + lane + 32] = so * (1.f / 6.f) + bias[lane + 32];
}

// ---------------- transpose x2 [NN,64] -> x2t [64,NN] (into g_xp) ------------
__global__ void k_transpose() {
    __shared__ float tile[32][33];
    int nb = blockIdx.x * 32, db = blockIdx.y * 32;
    int tx = threadIdx.x, ty = threadIdx.y;
#pragma unroll
    for (int i = ty; i < 32; i += 8) {
        int n = nb + i;
        tile[i][tx] = (n < NN) ? g_x2[(size_t)n * D + db + tx] : 0.f;
    }
    __syncthreads();
#pragma unroll
    for (int i = ty; i < 32; i += 8) {
        int n = nb + tx;
        if (n < NN) g_xp[(size_t)(db + i) * NN + n] = tile[tx][i];
    }
}

__global__ void k_zero_pool() {
    int i = blockIdx.x * blockDim.x + threadIdx.x;
    if (i < BATCH * D) g_pool[i] = 0.f;
}

// ---------------- pool = item @ x2   ([1024,50000] @ [50000,64]) -------------
// grid (64 b-tiles of 16, 4 n-splits); block 256 = 16 d-groups x 16 n-subsplits
__global__ void __launch_bounds__(256) k_pool(const float* __restrict__ item) {
    __shared__ float sit[16][64];
    int t = threadIdx.x;
    int b0 = blockIdx.x * 16;
    int nbase = blockIdx.y * (NN / 4);
    int nend  = nbase + (NN / 4);
    int g = t >> 4;        // d-group: d = 4g..4g+3
    int q = t & 15;        // n sub-index
    const float* __restrict__ x2t = g_xp;
    float acc[64];
#pragma unroll
    for (int i = 0; i < 64; i++) acc[i] = 0.f;

    for (int nb0 = nbase; nb0 < nend; nb0 += 64) {
        __syncthreads();
        // fill item chunk: thread (g as b-row, q as quad) loads float4
        int n4 = nb0 + 4 * q;
        float4 v = make_float4(0.f, 0.f, 0.f, 0.f);
        if (n4 < nend) v = *(const float4*)(item + (size_t)(b0 + g) * NN + n4);
        *(float4*)&sit[g][4 * q] = v;
        __syncthreads();

        int n0 = nb0 + 4 * q;
        float4 xv[4];
#pragma unroll
        for (int dd = 0; dd < 4; dd++)
            xv[dd] = *(const float4*)(x2t + (size_t)(4 * g + dd) * NN + n0);
#pragma unroll
        for (int bb = 0; bb < 16; bb++) {
            float4 it = *(const float4*)&sit[bb][4 * q];
#pragma unroll
            for (int dd = 0; dd < 4; dd++) {
                acc[bb * 4 + dd] += it.x * xv[dd].x + it.y * xv[dd].y +
                                    it.z * xv[dd].z + it.w * xv[dd].w;
            }
        }
    }
#pragma unroll
    for (int bb = 0; bb < 16; bb++)
#pragma unroll
        for (int dd = 0; dd < 4; dd++)
            atomicAdd(&g_pool[(b0 + bb) * D + 4 * g + dd], acc[bb * 4 + dd]);
}

// ---------------- MLP head + sigmoid -----------------------------------------
__global__ void __launch_bounds__(128) k_mlp(const int* __restrict__ user,
                                             const float* __restrict__ u_table,
                                             const float* __restrict__ W0,
                                             const float* __restrict__ b0,
                                             const float* __restrict__ W1,
                                             const float* __restrict__ b1,
                                             float* __restrict__ out) {
    __shared__ float vec[128];
    __shared__ float red[128];
    int b = blockIdx.x, t = threadIdx.x;
    if (t < 64) vec[t] = u_table[(size_t)user[b] * 64 + t];
    else        vec[t] = g_pool[b * 64 + (t - 64)];
    __syncthreads();
    float h = b0[t];
#pragma unroll 8
    for (int k = 0; k < 128; k++) h += vec[k] * W0[k * 128 + t];
    red[t] = h * W1[t];
    __syncthreads();
    for (int s = 64; s; s >>= 1) {
        if (t < s) red[t] += red[t + s];
        __syncthreads();
    }
    if (t == 0) {
        float z = red[0] + b1[0];
        out[b] = 1.f / (1.f + expf(-z));
    }
}

// ---------------- launch -----------------------------------------------------
extern "C" void kernel_launch(void* const* d_in, const int* in_sizes, int n_in,
                              void* d_out, int out_size) {
    const int*   user  = (const int*)d_in[0];
    const float* item  = (const float*)d_in[1];
    const int*   eidx  = (const int*)d_in[3];
    const float* u_tab = (const float*)d_in[4];
    const float* i_tab = (const float*)d_in[5];
    const float* W0    = (const float*)d_in[6];
    const float* as0   = (const float*)d_in[7];
    const float* ad0   = (const float*)d_in[8];
    const float* b0    = (const float*)d_in[9];
    const float* W1    = (const float*)d_in[10];
    const float* as1   = (const float*)d_in[11];
    const float* ad1   = (const float*)d_in[12];
    const float* b1    = (const float*)d_in[13];
    const float* lW0   = (const float*)d_in[14];
    const float* lb0   = (const float*)d_in[15];
    const float* lW1   = (const float*)d_in[16];
    const float* lb1   = (const float*)d_in[17];
    float* out = (float*)d_out;

    // CSR by destination
    k_init_deg<<<(NN + 255) / 256, 256>>>();
    k_count<<<(NE + 255) / 256, 256>>>(eidx);
    k_scan<<<1, 1024>>>();
    k_scatter<<<(ET + 255) / 256, 256>>>(eidx);

    // GAT layer 0 (input = i_table)
    k_gemm_xp<<<NN / 16, 384>>>(i_tab, W0, 0);
    k_attn<<<6250, 256>>>(as0, ad0);
    k_edge_ms<<<6250, 256>>>();
    k_edge_acc<<<6250, 256>>>(b0, 0);

    // GAT layer 1 (input = g_x1)
    k_gemm_xp<<<NN / 16, 384>>>(i_tab, W1, 1);
    k_attn<<<6250, 256>>>(as1, ad1);
    k_edge_ms<<<6250, 256>>>();
    k_edge_acc<<<6250, 256>>>(b1, 1);

    // pooling GEMM + MLP head
    k_transpose<<<dim3((NN + 31) / 32, 2), dim3(32, 8)>>>();
    k_zero_pool<<<(BATCH * D + 255) / 256, 256>>>();
    k_pool<<<dim3(BATCH / 16, 4), 256>>>(item);
    k_mlp<<<BATCH, 128>>>(user, u_tab, lW0, lb0, lW1, lb1, out);
}